// round 16
// baseline (speedup 1.0000x reference)
#include <cuda_runtime.h>
#include <cuda_fp16.h>

#define B_ 256
#define P_ 2048
#define C_ 10
#define O_ 16
#define I_ 8
#define PCH 32               // p's per routing/reduction chunk
#define NCHUNK (P_ / PCH)    // 64 chunks
#define SSZ (B_ * C_ * O_)   // 40960
#define RSTRIDE 336          // padded record stride in stage smem (bytes)
#define JJ 4                 // p-unroll in routing
#define PFD 8                // prefetch distance: 8 optimal (16 regressed, R14)
#define REC4 (B_ * 20)       // uint4 per p-slab (5120)

// u_hat fp16, layout [p][b][c][o2]: one (b,p) record = 320B contiguous.
__device__ __align__(16) __half2 g_uhat[(size_t)P_ * B_ * C_ * (O_ / 2)];
// Per-p-chunk partial s sums (plain stores, no atomics): [chunk][b][c][o].
__device__ __align__(16) float g_part[(size_t)NCHUNK * SSZ];
__device__ __align__(16) float g_vsum[SSZ];

typedef unsigned long long ull;

__device__ __forceinline__ ull ffma2(ull a, ull b, ull c) {
    ull d;
    asm("fma.rn.f32x2 %0, %1, %2, %3;" : "=l"(d) : "l"(a), "l"(b), "l"(c));
    return d;
}
__device__ __forceinline__ ull fadd2(ull a, ull b) {
    ull d;
    asm("add.rn.f32x2 %0, %1, %2;" : "=l"(d) : "l"(a), "l"(b));
    return d;
}
__device__ __forceinline__ ull pack2(float x, float y) {
    ull r;
    asm("mov.b64 %0, {%1, %2};" : "=l"(r) : "f"(x), "f"(y));
    return r;
}
__device__ __forceinline__ float2 unpack2(ull a) {
    float2 f;
    asm("mov.b64 {%0, %1}, %2;" : "=f"(f.x), "=f"(f.y) : "l"(a));
    return f;
}
__device__ __forceinline__ float rcp_fast(float x) {
    float r;
    asm("rcp.approx.f32 %0, %1;" : "=f"(r) : "f"(x));
    return r;
}
__device__ __forceinline__ float ex2_fast(float x) {
    float r;
    asm("ex2.approx.f32 %0, %1;" : "=f"(r) : "f"(x));
    return r;
}
__device__ __forceinline__ void prefetch_l2(const void* p) {
    asm volatile("prefetch.global.L2 [%0];" :: "l"(p));
}
// Streaming (evict-first) 16B load/store: single-use data, don't let it
// displace useful cache content. (ldcs in sum1/route: measured win, R15.)
__device__ __forceinline__ uint4 ldcs16(const uint4* p) {
    uint4 v;
    asm volatile("ld.global.cs.v4.u32 {%0,%1,%2,%3}, [%4];"
                 : "=r"(v.x), "=r"(v.y), "=r"(v.z), "=r"(v.w) : "l"(p));
    return v;
}
__device__ __forceinline__ void stcs16(uint4* p, uint4 v) {
    asm volatile("st.global.cs.v4.u32 [%0], {%1,%2,%3,%4};"
                 :: "l"(p), "r"(v.x), "r"(v.y), "r"(v.z), "r"(v.w));
}
__device__ __forceinline__ float4 ldcs16f(const float4* p) {
    float4 v;
    asm volatile("ld.global.cs.v4.f32 {%0,%1,%2,%3}, [%4];"
                 : "=f"(v.x), "=f"(v.y), "=f"(v.z), "=f"(v.w) : "l"(p));
    return v;
}
__device__ __forceinline__ void stcs16f(float4* p, float4 v) {
    asm volatile("st.global.cs.v4.f32 [%0], {%1,%2,%3,%4};"
                 :: "l"(p), "f"(v.x), "f"(v.y), "f"(v.z), "f"(v.w));
}
__device__ __forceinline__ float ldcs1f(const float* p) {
    float v;
    asm volatile("ld.global.cs.f32 %0, [%1];" : "=f"(v) : "l"(p));
    return v;
}

// ---------------------------------------------------------------------------
// K1: u_hat[p][b][c][o] = sum_i W[p,c,o,i]*u[b,p,i], fp16 out.
// One p per block, 256 threads. Thread t handles TWO b's (tb, tb+128) over
// FIVE c's -> each W LDS.128 feeds 2 b's. Results staged in padded smem
// (336B stride, conflict-free), then the 80KB p-slab flushed coalesced with
// STREAMING stores (output is consumed later chip-wide; keep L2 clean now).
// ---------------------------------------------------------------------------
__global__ void __launch_bounds__(256) k_uhat(const float* __restrict__ u,
                                              const float* __restrict__ W) {
    extern __shared__ char sm[];
    float* Ws = (float*)sm;                    // [c][i][o], 1280 floats
    char* stage = sm + C_ * I_ * O_ * 4;       // 256 records * RSTRIDE

    const int t = threadIdx.x;
    const int p = blockIdx.x;
    const int tb = t & 127;                    // b0 = tb, b1 = tb + 128
    const int c0 = (t >> 7) * 5;               // 0 or 5

    // Load + transpose W[p] ([c][o][i] -> [c][i][o]); 320 float4s, streaming.
    {
        const float4* Wg = (const float4*)(W + (size_t)p * (C_ * O_ * I_));
#pragma unroll
        for (int k = 0; k < 2; k++) {
            int idx = t + k * 256;
            if (idx < (C_ * O_ * I_) / 4) {
                float4 w4 = ldcs16f(Wg + idx);
                int L = idx * 4;
                int i = L & 7;                 // 0 or 4
                int o = (L >> 3) & 15;
                int cw = L >> 7;
                float* dst = Ws + cw * (I_ * O_) + o;
                dst[(i + 0) * O_] = w4.x;
                dst[(i + 1) * O_] = w4.y;
                dst[(i + 2) * O_] = w4.z;
                dst[(i + 3) * O_] = w4.w;
            }
        }
    }

    // u[b0/b1, p, :] (32B each) packed for f32x2.
    ull uu0[I_], uu1[I_];
    {
        const float4* ug = (const float4*)u;
        float4 a = ug[((size_t)tb * P_ + p) * 2 + 0];
        float4 d = ug[((size_t)tb * P_ + p) * 2 + 1];
        uu0[0] = pack2(a.x, a.x); uu0[1] = pack2(a.y, a.y);
        uu0[2] = pack2(a.z, a.z); uu0[3] = pack2(a.w, a.w);
        uu0[4] = pack2(d.x, d.x); uu0[5] = pack2(d.y, d.y);
        uu0[6] = pack2(d.z, d.z); uu0[7] = pack2(d.w, d.w);
        a = ug[((size_t)(tb + 128) * P_ + p) * 2 + 0];
        d = ug[((size_t)(tb + 128) * P_ + p) * 2 + 1];
        uu1[0] = pack2(a.x, a.x); uu1[1] = pack2(a.y, a.y);
        uu1[2] = pack2(a.z, a.z); uu1[3] = pack2(a.w, a.w);
        uu1[4] = pack2(d.x, d.x); uu1[5] = pack2(d.y, d.y);
        uu1[6] = pack2(d.z, d.z); uu1[7] = pack2(d.w, d.w);
    }
    __syncthreads();

#pragma unroll 1
    for (int c = c0; c < c0 + 5; c++) {
        const ulonglong2* w2 = (const ulonglong2*)(Ws + c * (I_ * O_));
        ull a0[8], a1[8];
#pragma unroll
        for (int k = 0; k < 8; k++) { a0[k] = 0ULL; a1[k] = 0ULL; }
#pragma unroll
        for (int i = 0; i < I_; i++) {
            ulonglong2 q0 = w2[i * 4 + 0];
            ulonglong2 q1 = w2[i * 4 + 1];
            ulonglong2 q2 = w2[i * 4 + 2];
            ulonglong2 q3 = w2[i * 4 + 3];
            a0[0] = ffma2(q0.x, uu0[i], a0[0]);  a1[0] = ffma2(q0.x, uu1[i], a1[0]);
            a0[1] = ffma2(q0.y, uu0[i], a0[1]);  a1[1] = ffma2(q0.y, uu1[i], a1[1]);
            a0[2] = ffma2(q1.x, uu0[i], a0[2]);  a1[2] = ffma2(q1.x, uu1[i], a1[2]);
            a0[3] = ffma2(q1.y, uu0[i], a0[3]);  a1[3] = ffma2(q1.y, uu1[i], a1[3]);
            a0[4] = ffma2(q2.x, uu0[i], a0[4]);  a1[4] = ffma2(q2.x, uu1[i], a1[4]);
            a0[5] = ffma2(q2.y, uu0[i], a0[5]);  a1[5] = ffma2(q2.y, uu1[i], a1[5]);
            a0[6] = ffma2(q3.x, uu0[i], a0[6]);  a1[6] = ffma2(q3.x, uu1[i], a1[6]);
            a0[7] = ffma2(q3.y, uu0[i], a0[7]);  a1[7] = ffma2(q3.y, uu1[i], a1[7]);
        }
        {
            union { __half2 h[8]; uint4 q[2]; } ou;
#pragma unroll
            for (int k = 0; k < 8; k++) {
                float2 f = unpack2(a0[k]);
                ou.h[k] = __floats2half2_rn(f.x, f.y);
            }
            uint4* dst = (uint4*)(stage + tb * RSTRIDE + c * 32);
            dst[0] = ou.q[0];
            dst[1] = ou.q[1];
        }
        {
            union { __half2 h[8]; uint4 q[2]; } ou;
#pragma unroll
            for (int k = 0; k < 8; k++) {
                float2 f = unpack2(a1[k]);
                ou.h[k] = __floats2half2_rn(f.x, f.y);
            }
            uint4* dst = (uint4*)(stage + (tb + 128) * RSTRIDE + c * 32);
            dst[0] = ou.q[0];
            dst[1] = ou.q[1];
        }
    }
    __syncthreads();

    // Flush: 5120 uint4 (80KB) -> global, coalesced streaming stores.
    uint4* out4 = (uint4*)g_uhat + (size_t)p * REC4;
#pragma unroll
    for (int k = 0; k < 20; k++) {
        int g = t + k * 256;
        int b = g / 20;
        int j = g - b * 20;
        stcs16(out4 + g, *(const uint4*)(stage + b * RSTRIDE + j * 16));
    }
}

// ---------------------------------------------------------------------------
// Iter-1: s1 = 0.1 * sum_p u_hat, per p-chunk partials. Pure streaming
// reduction: thread = one 16B column of the [p][5120-uint4] matrix.
// Streaming loads+stores; NO prefetch (hurt in R11).
// ---------------------------------------------------------------------------
__global__ void __launch_bounds__(256) k_sum1() {
    const int col = blockIdx.x * 256 + threadIdx.x;      // 0..5119
    const int ch = blockIdx.y;

    const uint4* base = (const uint4*)g_uhat + (size_t)ch * PCH * REC4 + col;

    ull acc[4];
#pragma unroll
    for (int k = 0; k < 4; k++) acc[k] = 0ULL;

#pragma unroll 8
    for (int p = 0; p < PCH; p++) {
        uint4 q = ldcs16(base + (size_t)p * REC4);
        const __half2* h = (const __half2*)&q;
#pragma unroll
        for (int k = 0; k < 4; k++) {
            float2 f = __half22float2(h[k]);
            acc[k] = fadd2(acc[k], pack2(f.x, f.y));
        }
    }

    float4* dst = (float4*)(g_part + (size_t)ch * SSZ) + col * 2;
    float2 f0 = unpack2(acc[0]);
    float2 f1 = unpack2(acc[1]);
    float2 f2 = unpack2(acc[2]);
    float2 f3 = unpack2(acc[3]);
    stcs16f(dst + 0, make_float4(0.1f * f0.x, 0.1f * f0.y, 0.1f * f1.x, 0.1f * f1.y));
    stcs16f(dst + 1, make_float4(0.1f * f2.x, 0.1f * f2.y, 0.1f * f3.x, 0.1f * f3.y));
}

// ---------------------------------------------------------------------------
// Routing pass (iters 2,3), barrier-free. 16-lane group = one (b,p) record;
// lane = c (10 active). Softmax Z via shfl_xor butterfly; ex2 with log2e
// pre-folded into vsum. fp16 HFMA2 accumulation within 8-p sub-chunks.
// L2 prefetch PFD=8 + streaming record loads (both measured wins).
// ---------------------------------------------------------------------------
__global__ void __launch_bounds__(128, 8) k_route() {
    const int t = threadIdx.x;
    const int w = t >> 5;                 // warp 0..3
    const int h = (t >> 4) & 1;
    const int c16 = t & 15;
    const bool active = (c16 < C_);
    const int cc = active ? c16 : 0;
    const int b = blockIdx.y * 8 + w * 2 + h;
    const int p0 = blockIdx.x * PCH;

    __half2 vsh[8];
    {
        const float4* vp = (const float4*)(g_vsum + (b * C_ + cc) * O_);
        const float L2E = 1.4426950408889634f;
#pragma unroll
        for (int k = 0; k < 4; k++) {
            float4 v4 = vp[k];
            vsh[2 * k + 0] = __floats2half2_rn(v4.x * L2E, v4.y * L2E);
            vsh[2 * k + 1] = __floats2half2_rn(v4.z * L2E, v4.w * L2E);
        }
    }

    ull acc[8];
#pragma unroll
    for (int k = 0; k < 8; k++) acc[k] = 0ULL;

    // Per-lane record offset (in __half2 units) within a p-slab.
    const size_t recoff = (size_t)b * (C_ * 8) + cc * 8;

#pragma unroll 1
    for (int sub = 0; sub < PCH / 8; sub++) {
        const int ph = p0 + sub * 8;
        __half2 acch[8];
#pragma unroll
        for (int k = 0; k < 8; k++) acch[k] = __floats2half2_rn(0.f, 0.f);

#pragma unroll
        for (int pj = 0; pj < 8; pj += JJ) {
            union { uint4 q[2]; __half2 h2[8]; } uu[JJ];
#pragma unroll
            for (int j = 0; j < JJ; j++) {
                const uint4* src =
                    (const uint4*)(g_uhat + (size_t)(ph + pj + j) * (B_ * C_ * 8) + recoff);
                uu[j].q[0] = ldcs16(src);
                uu[j].q[1] = ldcs16(src + 1);
            }
            // Prefetch PFD p's ahead into L2 (zero-register latency hiding).
#pragma unroll
            for (int j = 0; j < JJ; j++) {
                prefetch_l2(g_uhat + (size_t)(ph + pj + j + PFD) * (B_ * C_ * 8) + recoff);
            }

            float e[JJ], Z[JJ];
#pragma unroll
            for (int j = 0; j < JJ; j++) {
                __half2 lg = __floats2half2_rn(0.f, 0.f);
#pragma unroll
                for (int k = 0; k < 8; k++) lg = __hfma2(uu[j].h2[k], vsh[k], lg);
                float l = __low2float(lg) + __high2float(lg);
                e[j] = active ? ex2_fast(l) : 0.f;   // logit pre-scaled by log2e
                Z[j] = e[j];
            }
#pragma unroll
            for (int d = 1; d < 16; d <<= 1)
#pragma unroll
                for (int j = 0; j < JJ; j++)
                    Z[j] += __shfl_xor_sync(0xffffffffu, Z[j], d);

#pragma unroll
            for (int j = 0; j < JJ; j++) {
                __half2 cw2 = __float2half2_rn(e[j] * rcp_fast(Z[j]));
#pragma unroll
                for (int k = 0; k < 8; k++)
                    acch[k] = __hfma2(cw2, uu[j].h2[k], acch[k]);
            }
        }

        // Flush fp16 sub-chunk sums to f32x2 master accumulator.
#pragma unroll
        for (int k = 0; k < 8; k++) {
            float2 f = __half22float2(acch[k]);
            acc[k] = fadd2(acc[k], pack2(f.x, f.y));
        }
    }

    if (active) {
        float4* dst = (float4*)(g_part + (size_t)blockIdx.x * SSZ + (b * C_ + c16) * O_);
#pragma unroll
        for (int k = 0; k < 4; k++) {
            float2 f0 = unpack2(acc[2 * k + 0]);
            float2 f1 = unpack2(acc[2 * k + 1]);
            stcs16f(dst + k, make_float4(f0.x, f0.y, f1.x, f1.y));
        }
    }
}

// ---------------------------------------------------------------------------
// Squash: sum the NCHUNK partials (streaming reads), then squash.
// MODE 0: vsum=v.  MODE 1: vsum+=v.  MODE 2: out=v.
// ---------------------------------------------------------------------------
template <int MODE>
__global__ void __launch_bounds__(640) k_squash(float* __restrict__ out) {
    const int idx = blockIdx.x * 640 + threadIdx.x;

    float sv = 0.f;
#pragma unroll 8
    for (int k = 0; k < NCHUNK; k++) sv += ldcs1f(g_part + (size_t)k * SSZ + idx);

    float n2 = sv * sv;
#pragma unroll
    for (int d = 1; d < 16; d <<= 1) n2 += __shfl_xor_sync(0xffffffffu, n2, d);

    float scale = (n2 / (1.f + n2)) * rsqrtf(n2 + 1e-9f);
    float v = sv * scale;

    if (MODE == 0) {
        g_vsum[idx] = v;
    } else if (MODE == 1) {
        g_vsum[idx] += v;
    } else {
        out[idx] = v;
    }
}

// ---------------------------------------------------------------------------
extern "C" void kernel_launch(void* const* d_in, const int* in_sizes, int n_in,
                              void* d_out, int out_size) {
    const float* u = (const float*)d_in[0];
    const float* W = (const float*)d_in[1];
    if (n_in >= 2 && in_sizes[0] == P_ * C_ * O_ * I_ && in_sizes[1] == B_ * P_ * I_) {
        const float* tmp = u; u = W; W = tmp;
    }
    float* out = (float*)d_out;

    const int uhat_smem = C_ * I_ * O_ * 4 + B_ * RSTRIDE;  // 5120 + 86016
    static int attr_set = 0;
    if (!attr_set) {
        cudaFuncSetAttribute(k_uhat, cudaFuncAttributeMaxDynamicSharedMemorySize,
                             uhat_smem);
        attr_set = 1;
    }

    dim3 rg(NCHUNK, B_ / 8);       // (64, 32) = 2048 blocks of 128 thr
    dim3 sg(REC4 / 256, NCHUNK);   // (20, 64) = 1280 blocks

    k_uhat<<<P_, 256, uhat_smem>>>(u, W);          // 2048 blocks

    k_sum1<<<sg, 256>>>();                         // iter 1 (uniform weights)
    k_squash<0><<<SSZ / 640, 640>>>(out);          // v1 -> vsum

    k_route<<<rg, 128>>>();                        // iter 2
    k_squash<1><<<SSZ / 640, 640>>>(out);          // vsum += v2

    k_route<<<rg, 128>>>();                        // iter 3
    k_squash<2><<<SSZ / 640, 640>>>(out);          // out = v3
}

// round 17
// speedup vs baseline: 1.0285x; 1.0285x over previous
#include <cuda_runtime.h>
#include <cuda_fp16.h>

#define B_ 256
#define P_ 2048
#define C_ 10
#define O_ 16
#define I_ 8
#define PCH 32               // p's per routing/reduction chunk
#define NCHUNK (P_ / PCH)    // 64 chunks
#define SSZ (B_ * C_ * O_)   // 40960
#define RSTRIDE 336          // padded record stride in stage smem (bytes)
#define JJ 4                 // p-unroll in routing
#define PFD 8                // prefetch distance: 8 optimal (16 regressed, R14)
#define REC4 (B_ * 20)       // uint4 per p-slab (5120)

// u_hat fp16, layout [p][b][c][o2]: one (b,p) record = 320B contiguous.
__device__ __align__(16) __half2 g_uhat[(size_t)P_ * B_ * C_ * (O_ / 2)];
// Per-p-chunk partial s sums (plain stores, no atomics): [chunk][b][c][o].
// NOTE: g_part (10.5MB) fits in L2 and is re-read by k_squash immediately —
// keep DEFAULT caching on its stores/loads (evict-first here cost 3us, R16).
__device__ __align__(16) float g_part[(size_t)NCHUNK * SSZ];
__device__ __align__(16) float g_vsum[SSZ];

typedef unsigned long long ull;

__device__ __forceinline__ ull ffma2(ull a, ull b, ull c) {
    ull d;
    asm("fma.rn.f32x2 %0, %1, %2, %3;" : "=l"(d) : "l"(a), "l"(b), "l"(c));
    return d;
}
__device__ __forceinline__ ull fadd2(ull a, ull b) {
    ull d;
    asm("add.rn.f32x2 %0, %1, %2;" : "=l"(d) : "l"(a), "l"(b));
    return d;
}
__device__ __forceinline__ ull pack2(float x, float y) {
    ull r;
    asm("mov.b64 %0, {%1, %2};" : "=l"(r) : "f"(x), "f"(y));
    return r;
}
__device__ __forceinline__ float2 unpack2(ull a) {
    float2 f;
    asm("mov.b64 {%0, %1}, %2;" : "=f"(f.x), "=f"(f.y) : "l"(a));
    return f;
}
__device__ __forceinline__ float rcp_fast(float x) {
    float r;
    asm("rcp.approx.f32 %0, %1;" : "=f"(r) : "f"(x));
    return r;
}
__device__ __forceinline__ float ex2_fast(float x) {
    float r;
    asm("ex2.approx.f32 %0, %1;" : "=f"(r) : "f"(x));
    return r;
}
__device__ __forceinline__ void prefetch_l2(const void* p) {
    asm volatile("prefetch.global.L2 [%0];" :: "l"(p));
}
// Streaming (evict-first) 16B load: for single-use CONSUMER loads only
// (route/sum1 record reads — measured win, R15). Do NOT use on stores or
// on data re-read soon (g_part, u_hat tail) — measured regression, R16.
__device__ __forceinline__ uint4 ldcs16(const uint4* p) {
    uint4 v;
    asm volatile("ld.global.cs.v4.u32 {%0,%1,%2,%3}, [%4];"
                 : "=r"(v.x), "=r"(v.y), "=r"(v.z), "=r"(v.w) : "l"(p));
    return v;
}

// ---------------------------------------------------------------------------
// K1: u_hat[p][b][c][o] = sum_i W[p,c,o,i]*u[b,p,i], fp16 out.
// One p per block, 256 threads. Thread t handles TWO b's (tb, tb+128) over
// FIVE c's -> each W LDS.128 feeds 2 b's. Results staged in padded smem
// (336B stride, conflict-free), then the 80KB p-slab flushed coalesced with
// DEFAULT stores (tail stays L2-resident for k_sum1).
// ---------------------------------------------------------------------------
__global__ void __launch_bounds__(256) k_uhat(const float* __restrict__ u,
                                              const float* __restrict__ W) {
    extern __shared__ char sm[];
    float* Ws = (float*)sm;                    // [c][i][o], 1280 floats
    char* stage = sm + C_ * I_ * O_ * 4;       // 256 records * RSTRIDE

    const int t = threadIdx.x;
    const int p = blockIdx.x;
    const int tb = t & 127;                    // b0 = tb, b1 = tb + 128
    const int c0 = (t >> 7) * 5;               // 0 or 5

    // Load + transpose W[p] ([c][o][i] -> [c][i][o]); 320 float4s.
    {
        const float4* Wg = (const float4*)(W + (size_t)p * (C_ * O_ * I_));
#pragma unroll
        for (int k = 0; k < 2; k++) {
            int idx = t + k * 256;
            if (idx < (C_ * O_ * I_) / 4) {
                float4 w4 = Wg[idx];
                int L = idx * 4;
                int i = L & 7;                 // 0 or 4
                int o = (L >> 3) & 15;
                int cw = L >> 7;
                float* dst = Ws + cw * (I_ * O_) + o;
                dst[(i + 0) * O_] = w4.x;
                dst[(i + 1) * O_] = w4.y;
                dst[(i + 2) * O_] = w4.z;
                dst[(i + 3) * O_] = w4.w;
            }
        }
    }

    // u[b0/b1, p, :] (32B each) packed for f32x2.
    ull uu0[I_], uu1[I_];
    {
        const float4* ug = (const float4*)u;
        float4 a = ug[((size_t)tb * P_ + p) * 2 + 0];
        float4 d = ug[((size_t)tb * P_ + p) * 2 + 1];
        uu0[0] = pack2(a.x, a.x); uu0[1] = pack2(a.y, a.y);
        uu0[2] = pack2(a.z, a.z); uu0[3] = pack2(a.w, a.w);
        uu0[4] = pack2(d.x, d.x); uu0[5] = pack2(d.y, d.y);
        uu0[6] = pack2(d.z, d.z); uu0[7] = pack2(d.w, d.w);
        a = ug[((size_t)(tb + 128) * P_ + p) * 2 + 0];
        d = ug[((size_t)(tb + 128) * P_ + p) * 2 + 1];
        uu1[0] = pack2(a.x, a.x); uu1[1] = pack2(a.y, a.y);
        uu1[2] = pack2(a.z, a.z); uu1[3] = pack2(a.w, a.w);
        uu1[4] = pack2(d.x, d.x); uu1[5] = pack2(d.y, d.y);
        uu1[6] = pack2(d.z, d.z); uu1[7] = pack2(d.w, d.w);
    }
    __syncthreads();

#pragma unroll 1
    for (int c = c0; c < c0 + 5; c++) {
        const ulonglong2* w2 = (const ulonglong2*)(Ws + c * (I_ * O_));
        ull a0[8], a1[8];
#pragma unroll
        for (int k = 0; k < 8; k++) { a0[k] = 0ULL; a1[k] = 0ULL; }
#pragma unroll
        for (int i = 0; i < I_; i++) {
            ulonglong2 q0 = w2[i * 4 + 0];
            ulonglong2 q1 = w2[i * 4 + 1];
            ulonglong2 q2 = w2[i * 4 + 2];
            ulonglong2 q3 = w2[i * 4 + 3];
            a0[0] = ffma2(q0.x, uu0[i], a0[0]);  a1[0] = ffma2(q0.x, uu1[i], a1[0]);
            a0[1] = ffma2(q0.y, uu0[i], a0[1]);  a1[1] = ffma2(q0.y, uu1[i], a1[1]);
            a0[2] = ffma2(q1.x, uu0[i], a0[2]);  a1[2] = ffma2(q1.x, uu1[i], a1[2]);
            a0[3] = ffma2(q1.y, uu0[i], a0[3]);  a1[3] = ffma2(q1.y, uu1[i], a1[3]);
            a0[4] = ffma2(q2.x, uu0[i], a0[4]);  a1[4] = ffma2(q2.x, uu1[i], a1[4]);
            a0[5] = ffma2(q2.y, uu0[i], a0[5]);  a1[5] = ffma2(q2.y, uu1[i], a1[5]);
            a0[6] = ffma2(q3.x, uu0[i], a0[6]);  a1[6] = ffma2(q3.x, uu1[i], a1[6]);
            a0[7] = ffma2(q3.y, uu0[i], a0[7]);  a1[7] = ffma2(q3.y, uu1[i], a1[7]);
        }
        {
            union { __half2 h[8]; uint4 q[2]; } ou;
#pragma unroll
            for (int k = 0; k < 8; k++) {
                float2 f = unpack2(a0[k]);
                ou.h[k] = __floats2half2_rn(f.x, f.y);
            }
            uint4* dst = (uint4*)(stage + tb * RSTRIDE + c * 32);
            dst[0] = ou.q[0];
            dst[1] = ou.q[1];
        }
        {
            union { __half2 h[8]; uint4 q[2]; } ou;
#pragma unroll
            for (int k = 0; k < 8; k++) {
                float2 f = unpack2(a1[k]);
                ou.h[k] = __floats2half2_rn(f.x, f.y);
            }
            uint4* dst = (uint4*)(stage + (tb + 128) * RSTRIDE + c * 32);
            dst[0] = ou.q[0];
            dst[1] = ou.q[1];
        }
    }
    __syncthreads();

    // Flush: 5120 uint4 (80KB) -> global, fully coalesced (default policy).
    uint4* out4 = (uint4*)g_uhat + (size_t)p * REC4;
#pragma unroll
    for (int k = 0; k < 20; k++) {
        int g = t + k * 256;
        int b = g / 20;
        int j = g - b * 20;
        out4[g] = *(const uint4*)(stage + b * RSTRIDE + j * 16);
    }
}

// ---------------------------------------------------------------------------
// Iter-1: s1 = 0.1 * sum_p u_hat, per p-chunk partials. Pure streaming
// reduction: thread = one 16B column of the [p][5120-uint4] matrix.
// Streaming loads (single-use); default stores (g_part is L2-resident for
// squash). NO prefetch (hurt in R11).
// ---------------------------------------------------------------------------
__global__ void __launch_bounds__(256) k_sum1() {
    const int col = blockIdx.x * 256 + threadIdx.x;      // 0..5119
    const int ch = blockIdx.y;

    const uint4* base = (const uint4*)g_uhat + (size_t)ch * PCH * REC4 + col;

    ull acc[4];
#pragma unroll
    for (int k = 0; k < 4; k++) acc[k] = 0ULL;

#pragma unroll 8
    for (int p = 0; p < PCH; p++) {
        uint4 q = ldcs16(base + (size_t)p * REC4);
        const __half2* h = (const __half2*)&q;
#pragma unroll
        for (int k = 0; k < 4; k++) {
            float2 f = __half22float2(h[k]);
            acc[k] = fadd2(acc[k], pack2(f.x, f.y));
        }
    }

    float4* dst = (float4*)(g_part + (size_t)ch * SSZ) + col * 2;
    float2 f0 = unpack2(acc[0]);
    float2 f1 = unpack2(acc[1]);
    float2 f2 = unpack2(acc[2]);
    float2 f3 = unpack2(acc[3]);
    dst[0] = make_float4(0.1f * f0.x, 0.1f * f0.y, 0.1f * f1.x, 0.1f * f1.y);
    dst[1] = make_float4(0.1f * f2.x, 0.1f * f2.y, 0.1f * f3.x, 0.1f * f3.y);
}

// ---------------------------------------------------------------------------
// Routing pass (iters 2,3), barrier-free. 16-lane group = one (b,p) record;
// lane = c (10 active). Softmax Z via shfl_xor butterfly; ex2 with log2e
// pre-folded into vsum. fp16 HFMA2 accumulation within 8-p sub-chunks.
// L2 prefetch PFD=8 + streaming record loads (both measured wins).
// Default partial stores (g_part re-read by squash).
// ---------------------------------------------------------------------------
__global__ void __launch_bounds__(128, 8) k_route() {
    const int t = threadIdx.x;
    const int w = t >> 5;                 // warp 0..3
    const int h = (t >> 4) & 1;
    const int c16 = t & 15;
    const bool active = (c16 < C_);
    const int cc = active ? c16 : 0;
    const int b = blockIdx.y * 8 + w * 2 + h;
    const int p0 = blockIdx.x * PCH;

    __half2 vsh[8];
    {
        const float4* vp = (const float4*)(g_vsum + (b * C_ + cc) * O_);
        const float L2E = 1.4426950408889634f;
#pragma unroll
        for (int k = 0; k < 4; k++) {
            float4 v4 = vp[k];
            vsh[2 * k + 0] = __floats2half2_rn(v4.x * L2E, v4.y * L2E);
            vsh[2 * k + 1] = __floats2half2_rn(v4.z * L2E, v4.w * L2E);
        }
    }

    ull acc[8];
#pragma unroll
    for (int k = 0; k < 8; k++) acc[k] = 0ULL;

    // Per-lane record offset (in __half2 units) within a p-slab.
    const size_t recoff = (size_t)b * (C_ * 8) + cc * 8;

#pragma unroll 1
    for (int sub = 0; sub < PCH / 8; sub++) {
        const int ph = p0 + sub * 8;
        __half2 acch[8];
#pragma unroll
        for (int k = 0; k < 8; k++) acch[k] = __floats2half2_rn(0.f, 0.f);

#pragma unroll
        for (int pj = 0; pj < 8; pj += JJ) {
            union { uint4 q[2]; __half2 h2[8]; } uu[JJ];
#pragma unroll
            for (int j = 0; j < JJ; j++) {
                const uint4* src =
                    (const uint4*)(g_uhat + (size_t)(ph + pj + j) * (B_ * C_ * 8) + recoff);
                uu[j].q[0] = ldcs16(src);
                uu[j].q[1] = ldcs16(src + 1);
            }
            // Prefetch PFD p's ahead into L2 (zero-register latency hiding).
#pragma unroll
            for (int j = 0; j < JJ; j++) {
                prefetch_l2(g_uhat + (size_t)(ph + pj + j + PFD) * (B_ * C_ * 8) + recoff);
            }

            float e[JJ], Z[JJ];
#pragma unroll
            for (int j = 0; j < JJ; j++) {
                __half2 lg = __floats2half2_rn(0.f, 0.f);
#pragma unroll
                for (int k = 0; k < 8; k++) lg = __hfma2(uu[j].h2[k], vsh[k], lg);
                float l = __low2float(lg) + __high2float(lg);
                e[j] = active ? ex2_fast(l) : 0.f;   // logit pre-scaled by log2e
                Z[j] = e[j];
            }
#pragma unroll
            for (int d = 1; d < 16; d <<= 1)
#pragma unroll
                for (int j = 0; j < JJ; j++)
                    Z[j] += __shfl_xor_sync(0xffffffffu, Z[j], d);

#pragma unroll
            for (int j = 0; j < JJ; j++) {
                __half2 cw2 = __float2half2_rn(e[j] * rcp_fast(Z[j]));
#pragma unroll
                for (int k = 0; k < 8; k++)
                    acch[k] = __hfma2(cw2, uu[j].h2[k], acch[k]);
            }
        }

        // Flush fp16 sub-chunk sums to f32x2 master accumulator.
#pragma unroll
        for (int k = 0; k < 8; k++) {
            float2 f = __half22float2(acch[k]);
            acc[k] = fadd2(acc[k], pack2(f.x, f.y));
        }
    }

    if (active) {
        float4* dst = (float4*)(g_part + (size_t)blockIdx.x * SSZ + (b * C_ + c16) * O_);
#pragma unroll
        for (int k = 0; k < 4; k++) {
            float2 f0 = unpack2(acc[2 * k + 0]);
            float2 f1 = unpack2(acc[2 * k + 1]);
            dst[k] = make_float4(f0.x, f0.y, f1.x, f1.y);
        }
    }
}

// ---------------------------------------------------------------------------
// Squash: sum the NCHUNK partials (default-cached, L2-resident), then
// squash. MODE 0: vsum=v.  MODE 1: vsum+=v.  MODE 2: out=v.
// ---------------------------------------------------------------------------
template <int MODE>
__global__ void __launch_bounds__(640) k_squash(float* __restrict__ out) {
    const int idx = blockIdx.x * 640 + threadIdx.x;

    float sv = 0.f;
#pragma unroll 8
    for (int k = 0; k < NCHUNK; k++) sv += g_part[(size_t)k * SSZ + idx];

    float n2 = sv * sv;
#pragma unroll
    for (int d = 1; d < 16; d <<= 1) n2 += __shfl_xor_sync(0xffffffffu, n2, d);

    float scale = (n2 / (1.f + n2)) * rsqrtf(n2 + 1e-9f);
    float v = sv * scale;

    if (MODE == 0) {
        g_vsum[idx] = v;
    } else if (MODE == 1) {
        g_vsum[idx] += v;
    } else {
        out[idx] = v;
    }
}

// ---------------------------------------------------------------------------
extern "C" void kernel_launch(void* const* d_in, const int* in_sizes, int n_in,
                              void* d_out, int out_size) {
    const float* u = (const float*)d_in[0];
    const float* W = (const float*)d_in[1];
    if (n_in >= 2 && in_sizes[0] == P_ * C_ * O_ * I_ && in_sizes[1] == B_ * P_ * I_) {
        const float* tmp = u; u = W; W = tmp;
    }
    float* out = (float*)d_out;

    const int uhat_smem = C_ * I_ * O_ * 4 + B_ * RSTRIDE;  // 5120 + 86016
    static int attr_set = 0;
    if (!attr_set) {
        cudaFuncSetAttribute(k_uhat, cudaFuncAttributeMaxDynamicSharedMemorySize,
                             uhat_smem);
        attr_set = 1;
    }

    dim3 rg(NCHUNK, B_ / 8);       // (64, 32) = 2048 blocks of 128 thr
    dim3 sg(REC4 / 256, NCHUNK);   // (20, 64) = 1280 blocks

    k_uhat<<<P_, 256, uhat_smem>>>(u, W);          // 2048 blocks

    k_sum1<<<sg, 256>>>();                         // iter 1 (uniform weights)
    k_squash<0><<<SSZ / 640, 640>>>(out);          // v1 -> vsum

    k_route<<<rg, 128>>>();                        // iter 2
    k_squash<1><<<SSZ / 640, 640>>>(out);          // vsum += v2

    k_route<<<rg, 128>>>();                        // iter 3
    k_squash<2><<<SSZ / 640, 640>>>(out);          // out = v3
}